// round 13
// baseline (speedup 1.0000x reference)
#include <cuda_runtime.h>
#include <cuda_fp16.h>
#include <cstdint>

#define LOG2F_ 0.6931471805599453f

// ---------------- scratch (__device__ globals) --------------------------------
__device__ float g_h[32768 * 64];
__device__ float g_z[32768 * 192];
__device__ float g_hWt[128 * 64];
__device__ float g_Gt[192 * 128];
__device__ float g_gbsum[128];

// ---------------- helpers -----------------------------------------------------
__device__ __forceinline__ unsigned f2tf(float f) {
    unsigned r;
    asm("cvt.rna.tf32.f32 %0, %1;" : "=r"(r) : "f"(f));
    return r;
}
__device__ __forceinline__ float sspf(float v) {
    return fmaxf(v, 0.f) + __logf(1.f + __expf(-fabsf(v))) - LOG2F_;
}
__device__ __forceinline__ void mma8(float d[4], unsigned a0, unsigned a1,
                                     unsigned a2, unsigned a3,
                                     unsigned b0, unsigned b1) {
    asm volatile(
        "mma.sync.aligned.m16n8k8.row.col.f32.tf32.tf32.f32 "
        "{%0,%1,%2,%3}, {%4,%5,%6,%7}, {%8,%9}, {%0,%1,%2,%3};"
        : "+f"(d[0]), "+f"(d[1]), "+f"(d[2]), "+f"(d[3])
        : "r"(a0), "r"(a1), "r"(a2), "r"(a3), "r"(b0), "r"(b1));
}
// packed A-fragment addr for element (row h, col j) of 16x8 tiles, stride 128
__device__ __forceinline__ int atIdx(int h, int j) {
    return (((h >> 4) * 2 + (j >> 4)) * 2 + ((j >> 3) & 1)) * 128
         + ((h & 7) * 4 + (j & 3)) * 4 + ((h >> 3) & 1) + ((j & 4) >> 1);
}

// ---------------- init --------------------------------------------------------
__global__ void init_kernel(const float* __restrict__ X, float* __restrict__ out) {
    size_t g = (size_t)blockIdx.x * blockDim.x + threadIdx.x;
    out[g] = X[g & 127];
}

// ---------------- per-layer weight prep ---------------------------------------
__global__ void prep_kernel(const float* __restrict__ hW, const float* __restrict__ gW,
                            const float* __restrict__ gb, int l) {
    int g = blockIdx.x * blockDim.x + threadIdx.x;
    if (g < 8192) {
        int d = g >> 6, k = g & 63;
        g_hWt[g] = hW[(l * 64 + k) * 128 + d];
    }
    if (g < 24576) {
        int kc = g >> 7, d = g & 127;
        int c = kc >> 6, k = kc & 63;
        g_Gt[g] = gW[((l * 3 + c) * 128 + d) * 64 + k];
    }
    if (g < 128) {
        g_gbsum[g] = gb[(l * 3 + 0) * 128 + g] + gb[(l * 3 + 1) * 128 + g]
                   + gb[(l * 3 + 2) * 128 + g];
    }
}

// ---------------- generic tiled GEMM ------------------------------------------
__global__ __launch_bounds__(128) void gemm_kernel(
    const float* __restrict__ A, const float* __restrict__ B,
    const float* __restrict__ bias, float* __restrict__ C,
    int M, int K, int N, int accumulate)
{
    __shared__ __align__(16) float As[16][64];
    __shared__ __align__(16) float Bs[16][64];
    int t = threadIdx.x;
    int mT = blockIdx.x * 64, nT = blockIdx.y * 64;
    int tx = t & 7, ty = t >> 3;
    float acc[4][8];
#pragma unroll
    for (int r = 0; r < 4; r++)
#pragma unroll
        for (int c = 0; c < 8; c++) acc[r][c] = 0.f;

    for (int k0 = 0; k0 < K; k0 += 16) {
        {
            int row = t >> 1, kq = (t & 1) * 8;
            const float* ap = A + (size_t)(mT + row) * K + k0 + kq;
            float4 a0 = *(const float4*)ap;
            float4 a1 = *(const float4*)(ap + 4);
            As[kq + 0][row] = a0.x; As[kq + 1][row] = a0.y;
            As[kq + 2][row] = a0.z; As[kq + 3][row] = a0.w;
            As[kq + 4][row] = a1.x; As[kq + 5][row] = a1.y;
            As[kq + 6][row] = a1.z; As[kq + 7][row] = a1.w;
        }
        {
            int kr = t >> 3, nq = (t & 7) * 8;
            const float* bp = B + (size_t)(k0 + kr) * N + nT + nq;
            *(float4*)&Bs[kr][nq]     = *(const float4*)bp;
            *(float4*)&Bs[kr][nq + 4] = *(const float4*)(bp + 4);
        }
        __syncthreads();
#pragma unroll
        for (int kk = 0; kk < 16; kk++) {
            float4 a  = *(float4*)&As[kk][ty * 4];
            float4 b0 = *(float4*)&Bs[kk][tx * 8];
            float4 b1 = *(float4*)&Bs[kk][tx * 8 + 4];
            float av[4] = {a.x, a.y, a.z, a.w};
            float bv[8] = {b0.x, b0.y, b0.z, b0.w, b1.x, b1.y, b1.z, b1.w};
#pragma unroll
            for (int r = 0; r < 4; r++)
#pragma unroll
                for (int c = 0; c < 8; c++) acc[r][c] += av[r] * bv[c];
        }
        __syncthreads();
    }
#pragma unroll
    for (int r = 0; r < 4; r++) {
        int m = mT + ty * 4 + r;
        float* cp = C + (size_t)m * N + nT + tx * 8;
#pragma unroll
        for (int c = 0; c < 8; c++) {
            float v = acc[r][c] + bias[nT + tx * 8 + c];
            if (accumulate) v += cp[c];
            cp[c] = v;
        }
    }
}

// ---------------- tf32 MMA message kernel (lean + W2-in-smem) -------------------
// Grid 2048: block = (b, ihalf). 8 warps. Dynamic smem 55744 B:
//  buf[0..8192) words | Hs[8192..10272) | W2h (half) [10272..13472) |
//  b1s[13472..13616) | b2e[13616..13744) | Hsum[13744..13872) | Ysum[13872..13936)
__global__ __launch_bounds__(256, 4) void msg_mma_kernel(
    const float* __restrict__ Ee, const float* __restrict__ Enuc,
    const float* __restrict__ wW1, const float* __restrict__ wb1,
    const float* __restrict__ wW2, const float* __restrict__ wb2,
    const float* __restrict__ Yp, int l)
{
    extern __shared__ __align__(16) unsigned dsm[];
    unsigned* buf  = dsm;                          // 8192 words
    float*    Hs   = (float*)(dsm + 8192);         // 2080 (stride 65)
    __half*   W2h  = (__half*)(dsm + 10272);       // 6400 halves (2 x 64 x 50)
    float*    b1s  = (float*)(dsm + 13472);        // 144
    float*    b2e  = (float*)(dsm + 13616);        // 128
    float*    Hsum = (float*)(dsm + 13744);        // 128
    float*    Ysum = (float*)(dsm + 13872);        // 64

    const int b = blockIdx.x >> 1, ihalf = blockIdx.x & 1;
    const int t = threadIdx.x, w = t >> 5, lane = t & 31;
    const int g = lane >> 2, tg = lane & 3;
    const int cls = w & 1, n0 = (w >> 1) * 2;
    const int i0 = ihalf * 16;

    // ---- fill smem ----
    for (int idx = t; idx < 2048; idx += 256) {
        int j = idx >> 6, k = idx & 63;
        Hs[j * 65 + k] = __uint_as_float(f2tf(g_h[(size_t)b * 2048 + idx]));
    }
    for (int idx = t; idx < 135; idx += 256)
        b1s[(idx / 45) * 48 + idx % 45] = wb1[l * 135 + idx];
    for (int idx = t; idx < 1536; idx += 256)   // AtP zero (h>=45 rows must stay 0)
        buf[2048 + idx] = 0u;
    for (int idx = t; idx < 3072; idx += 256) {   // W1 fragments, ch 0,1
        int tile = idx >> 6, l2 = idx & 63;
        int c = tile / 24, r = tile % 24;
        int nt = r >> 2, kt = r & 3;
        int ln = l2 >> 1, s = l2 & 1;
        int h = nt * 8 + (ln >> 2), f = kt * 8 + (ln & 3) + 4 * s;
        buf[3584 + idx] = (h < 45)
            ? f2tf(__ldg(&wW1[((size_t)(l * 3 + c) * 45 + h) * 32 + f])) : 0u;
    }
    for (int idx = t; idx < 6400; idx += 256) {   // W2 as fp16, padded rows of 50
        int ck = idx / 50, h = idx % 50;
        int c = ck >> 6, k = ck & 63;
        W2h[idx] = (h < 45)
            ? __float2half(__ldg(&wW2[((size_t)(l * 3 + c) * 64 + k) * 45 + h]))
            : __float2half(0.f);
    }
    if (t < 128) b2e[t] = wb2[l * 192 + t];       // channels 0,1
    __syncthreads();
    if (t < 128) {
        int c = t >> 6, k = t & 63;
        float s = 0.f;
        for (int j = 0; j < 16; j++) s += Hs[(c * 16 + j) * 65 + k];
        Hsum[t] = s;
    }
    if (t < 64) {
        float s = 0.f;
        for (int m = 0; m < 4; m++) s += __ldg(&Yp[m * 64 + t]);
        Ysum[t] = s;
    }
    // step-2 B fragments (loop-invariant, 8 regs)
    unsigned hbf[2][2][2];
#pragma unroll
    for (int ntl = 0; ntl < 2; ntl++)
#pragma unroll
        for (int kt = 0; kt < 2; kt++) {
            int jc = cls * 16 + kt * 8 + tg, kc = (n0 + ntl) * 8 + g;
            hbf[ntl][kt][0] = __float_as_uint(Hs[jc * 65 + kc]);
            hbf[ntl][kt][1] = __float_as_uint(Hs[(jc + 4) * 65 + kc]);
        }
    const int c3 = ((cls == 0) == (ihalf == 0)) ? 0 : 1;

    // ---- initial E load (buffer 0) ----
    {
        int j = t >> 3, f4 = t & 7;
        float4 e4 = *(const float4*)(Ee + (((size_t)(b * 32 + i0)) * 32 + j) * 32 + 4 * f4);
        unsigned* p = &buf[((j >> 4) * 4 + (f4 >> 1)) * 128 + (j & 7) * 16
                           + ((j >> 3) & 1) + 2 * (f4 & 1)];
        p[0] = f2tf(e4.x); p[4] = f2tf(e4.y); p[8] = f2tf(e4.z); p[12] = f2tf(e4.w);
    }
    __syncthreads();

    // ================= electron edges =================
    for (int ii = 0; ii < 16; ii++) {
        const int i = i0 + ii;
        const int cur = (ii & 1) * 1024;
        if (ii < 15) {   // prefetch next E into other buffer
            int j = t >> 3, f4 = t & 7;
            float4 e4 = *(const float4*)(
                Ee + (((size_t)(b * 32 + i + 1)) * 32 + j) * 32 + 4 * f4);
            unsigned* p = &buf[(cur ^ 1024) + ((j >> 4) * 4 + (f4 >> 1)) * 128
                               + (j & 7) * 16 + ((j >> 3) & 1) + 2 * (f4 & 1)];
            p[0] = f2tf(e4.x); p[4] = f2tf(e4.y);
            p[8] = f2tf(e4.z); p[12] = f2tf(e4.w);
        }
        if (w < 6) {   // step1: A = ssp(E @ W1c^T + b1) -> AtP
#pragma unroll
            for (int mt = 0; mt < 2; mt++) {
                int c = ((mt == 0) == (ihalf == 0)) ? 0 : 1;
                float d[4] = {0.f, 0.f, 0.f, 0.f};
#pragma unroll
                for (int kt = 0; kt < 4; kt++) {
                    uint4 av = *(const uint4*)&buf[cur + (mt * 4 + kt) * 128 + lane * 4];
                    uint2 bv = *(const uint2*)&buf[3584 + (c * 24 + w * 4 + kt) * 64 + lane * 2];
                    mma8(d, av.x, av.y, av.z, av.w, bv.x, bv.y);
                }
                int h0 = w * 8 + 2 * tg, h1 = h0 + 1;
                int j0 = mt * 16 + g, j1 = j0 + 8;
                const float* bb = &b1s[c * 48];
                if (h0 < 45) {
                    buf[2048 + atIdx(h0, j0)] = (j0 == i) ? 0u : f2tf(sspf(d[0] + bb[h0]));
                    buf[2048 + atIdx(h0, j1)] = (j1 == i) ? 0u : f2tf(sspf(d[2] + bb[h0]));
                }
                if (h1 < 45) {
                    buf[2048 + atIdx(h1, j0)] = (j0 == i) ? 0u : f2tf(sspf(d[1] + bb[h1]));
                    buf[2048 + atIdx(h1, j1)] = (j1 == i) ? 0u : f2tf(sspf(d[3] + bb[h1]));
                }
            }
        }
        __syncthreads();
        {   // step2 + epilogue + writeout
            float acc[2][3][4];
#pragma unroll
            for (int ntl = 0; ntl < 2; ntl++)
#pragma unroll
                for (int mt = 0; mt < 3; mt++)
#pragma unroll
                    for (int q = 0; q < 4; q++) acc[ntl][mt][q] = 0.f;
#pragma unroll
            for (int mt = 0; mt < 3; mt++)
#pragma unroll
                for (int kt = 0; kt < 2; kt++) {
                    uint4 av = *(const uint4*)&buf[2048
                                 + ((mt * 2 + cls) * 2 + kt) * 128 + lane * 4];
                    mma8(acc[0][mt], av.x, av.y, av.z, av.w,
                         hbf[0][kt][0], hbf[0][kt][1]);
                    mma8(acc[1][mt], av.x, av.y, av.z, av.w,
                         hbf[1][kt][0], hbf[1][kt][1]);
                }
#pragma unroll
            for (int ntl = 0; ntl < 2; ntl++)
#pragma unroll
                for (int par = 0; par < 2; par++) {
                    int k = (n0 + ntl) * 8 + 2 * tg + par;
                    const __half* wph = &W2h[(c3 * 64 + k) * 50];
                    float s = 0.f;
#pragma unroll
                    for (int mt = 0; mt < 3; mt++) {
                        int h0 = mt * 16 + g;
                        s += acc[ntl][mt][par]     * __half2float(wph[h0]);
                        s += acc[ntl][mt][par + 2] * __half2float(wph[h0 + 8]);
                    }
                    s += __shfl_xor_sync(0xffffffffu, s, 4);
                    s += __shfl_xor_sync(0xffffffffu, s, 8);
                    s += __shfl_xor_sync(0xffffffffu, s, 16);
                    if (g == 0) {
                        float hsub = Hsum[cls * 64 + k]
                                   - ((cls == ihalf) ? Hs[i * 65 + k] : 0.f);
                        g_z[((size_t)(b * 32 + i) * 3 + c3) * 64 + k]
                            = s + b2e[c3 * 64 + k] * hsub;
                    }
                }
        }
        __syncthreads();
    }

    // ================= nuclear edges: 2 barriers total =================
    for (int idx = t; idx < 6144; idx += 256) buf[2048 + idx] = 0u;  // AtN zero
    {   // load E_nuc for all 16 i: row r = i_local*4 + m (64 rows x 32 f)
        int r = t >> 2, fb = (t & 3) * 8;
        const float* ep = Enuc + (((size_t)(b * 32 + i0 + (r >> 2))) * 4 + (r & 3)) * 32 + fb;
        float4 e0 = *(const float4*)ep;
        float4 e1 = *(const float4*)(ep + 4);
        unsigned* pb = &buf[((r >> 4) * 4 + (fb >> 3)) * 128];
        int lr = (r & 7) * 4, qr = (r >> 3) & 1;
        pb[(lr + 0) * 4 + qr]     = f2tf(e0.x);
        pb[(lr + 1) * 4 + qr]     = f2tf(e0.y);
        pb[(lr + 2) * 4 + qr]     = f2tf(e0.z);
        pb[(lr + 3) * 4 + qr]     = f2tf(e0.w);
        pb[(lr + 0) * 4 + qr + 2] = f2tf(e1.x);
        pb[(lr + 1) * 4 + qr + 2] = f2tf(e1.y);
        pb[(lr + 2) * 4 + qr + 2] = f2tf(e1.z);
        pb[(lr + 3) * 4 + qr + 2] = f2tf(e1.w);
    }
    __syncthreads();
    // phase A: step1 for all 16 i (24 tasks: mt 0..3 x nt 0..5)
#pragma unroll
    for (int s = 0; s < 3; s++) {
        int tau = w + 8 * s;
        int mt = tau / 6, nt = tau % 6;
        int hB = nt * 8 + g;
        float d[4] = {0.f, 0.f, 0.f, 0.f};
#pragma unroll
        for (int kt = 0; kt < 4; kt++) {
            uint4 av = *(const uint4*)&buf[(mt * 4 + kt) * 128 + lane * 4];
            unsigned bx = 0u, by = 0u;
            if (hB < 45) {
                const float* wp = &wW1[((size_t)(l * 3 + 2) * 45 + hB) * 32 + kt * 8 + tg];
                bx = f2tf(__ldg(wp)); by = f2tf(__ldg(wp + 4));
            }
            mma8(d, av.x, av.y, av.z, av.w, bx, by);
        }
        int h0 = nt * 8 + 2 * tg, h1 = h0 + 1;
        int r0 = mt * 16 + g, r1 = r0 + 8;
        if (h0 < 45) {
            buf[2048 + (r0 >> 2) * 384 + (h0 >> 4) * 128
                + (((h0 & 7) * 4 + (r0 & 3)) << 2) + ((h0 >> 3) & 1)]
                = f2tf(sspf(d[0] + b1s[96 + h0]));
            buf[2048 + (r1 >> 2) * 384 + (h0 >> 4) * 128
                + (((h0 & 7) * 4 + (r1 & 3)) << 2) + ((h0 >> 3) & 1)]
                = f2tf(sspf(d[2] + b1s[96 + h0]));
        }
        if (h1 < 45) {
            buf[2048 + (r0 >> 2) * 384 + (h1 >> 4) * 128
                + (((h1 & 7) * 4 + (r0 & 3)) << 2) + ((h1 >> 3) & 1)]
                = f2tf(sspf(d[1] + b1s[96 + h1]));
            buf[2048 + (r1 >> 2) * 384 + (h1 >> 4) * 128
                + (((h1 & 7) * 4 + (r1 & 3)) << 2) + ((h1 >> 3) & 1)]
                = f2tf(sspf(d[3] + b1s[96 + h1]));
        }
    }
    __syncthreads();
    // phase B: warp w owns k-tile w, sweeps all 16 i with no barriers
    {
        unsigned yb0 = f2tf(__ldg(&Yp[tg * 64 + w * 8 + g]));
        float w2n[2][3][2], b2n[2];
#pragma unroll
        for (int par = 0; par < 2; par++) {
            int k = w * 8 + 2 * tg + par;
            b2n[par] = __ldg(&wb2[(l * 3 + 2) * 64 + k]);
            const float* wp = wW2 + (size_t)((l * 3 + 2) * 64 + k) * 45;
#pragma unroll
            for (int mt = 0; mt < 3; mt++) {
                int h0 = mt * 16 + g, h1 = h0 + 8; if (h1 > 44) h1 = 44;
                w2n[par][mt][0] = __ldg(wp + h0);
                w2n[par][mt][1] = __ldg(wp + h1);
            }
        }
        for (int il = 0; il < 16; il++) {
            float facc[3][4];
#pragma unroll
            for (int mt = 0; mt < 3; mt++)
#pragma unroll
                for (int q = 0; q < 4; q++) facc[mt][q] = 0.f;
#pragma unroll
            for (int mt = 0; mt < 3; mt++) {
                uint4 av = *(const uint4*)&buf[2048 + il * 384 + mt * 128 + lane * 4];
                mma8(facc[mt], av.x, av.y, av.z, av.w, yb0, 0u);
            }
#pragma unroll
            for (int par = 0; par < 2; par++) {
                int k = w * 8 + 2 * tg + par;
                float s = 0.f;
#pragma unroll
                for (int mt = 0; mt < 3; mt++) {
                    s += facc[mt][par]     * w2n[par][mt][0];
                    s += facc[mt][par + 2] * w2n[par][mt][1];
                }
                s += __shfl_xor_sync(0xffffffffu, s, 4);
                s += __shfl_xor_sync(0xffffffffu, s, 8);
                s += __shfl_xor_sync(0xffffffffu, s, 16);
                if (g == 0) {
                    g_z[((size_t)(b * 32 + i0 + il) * 3 + 2) * 64 + k]
                        = s + b2n[par] * Ysum[k];
                }
            }
        }
    }
}

// ---------------- launch ------------------------------------------------------
extern "C" void kernel_launch(void* const* d_in, const int* in_sizes, int n_in,
                              void* d_out, int out_size) {
    const float* Ee  = (const float*)d_in[0];
    const float* En  = (const float*)d_in[1];
    const float* X   = (const float*)d_in[2];
    const float* Y   = (const float*)d_in[3];
    const float* wW1 = (const float*)d_in[4];
    const float* wb1 = (const float*)d_in[5];
    const float* wW2 = (const float*)d_in[6];
    const float* wb2 = (const float*)d_in[7];
    const float* hW  = (const float*)d_in[8];
    const float* hb  = (const float*)d_in[9];
    const float* gW  = (const float*)d_in[10];
    const float* gb  = (const float*)d_in[11];
    float* x = (float*)d_out;

    float *hbuf, *zbuf, *hWt, *Gt, *gbs;
    cudaGetSymbolAddress((void**)&hbuf, g_h);
    cudaGetSymbolAddress((void**)&zbuf, g_z);
    cudaGetSymbolAddress((void**)&hWt,  g_hWt);
    cudaGetSymbolAddress((void**)&Gt,   g_Gt);
    cudaGetSymbolAddress((void**)&gbs,  g_gbsum);

    const int MSG_SMEM = 13936 * 4;   // 55744 bytes
    cudaFuncSetAttribute(msg_mma_kernel,
                         cudaFuncAttributeMaxDynamicSharedMemorySize, MSG_SMEM);

    init_kernel<<<16384, 256>>>(X, x);
    for (int l = 0; l < 3; l++) {
        prep_kernel<<<96, 256>>>(hW, gW, gb, l);
        gemm_kernel<<<dim3(512, 1), 128>>>(x, hWt, hb + l * 64, hbuf,
                                           32768, 128, 64, 0);
        msg_mma_kernel<<<2048, 256, MSG_SMEM>>>(Ee, En, wW1, wb1, wW2, wb2, Y, l);
        gemm_kernel<<<dim3(512, 2), 128>>>(zbuf, Gt, gbs, x,
                                           32768, 192, 128, 1);
    }
}

// round 16
// speedup vs baseline: 1.4225x; 1.4225x over previous
#include <cuda_runtime.h>
#include <cstdint>

#define LOG2F_ 0.6931471805599453f

// ---------------- scratch (__device__ globals) --------------------------------
__device__ float g_h[32768 * 64];
__device__ float g_z[32768 * 192];
__device__ float g_hWt[128 * 64];
__device__ float g_Gt[192 * 128];
__device__ float g_gbsum[128];

// ---------------- helpers -----------------------------------------------------
__device__ __forceinline__ unsigned f2tf(float f) {
    unsigned r;
    asm("cvt.rna.tf32.f32 %0, %1;" : "=r"(r) : "f"(f));
    return r;
}
__device__ __forceinline__ float sspf(float v) {
    return fmaxf(v, 0.f) + __logf(1.f + __expf(-fabsf(v))) - LOG2F_;
}
__device__ __forceinline__ void mma8(float d[4], unsigned a0, unsigned a1,
                                     unsigned a2, unsigned a3,
                                     unsigned b0, unsigned b1) {
    asm volatile(
        "mma.sync.aligned.m16n8k8.row.col.f32.tf32.tf32.f32 "
        "{%0,%1,%2,%3}, {%4,%5,%6,%7}, {%8,%9}, {%0,%1,%2,%3};"
        : "+f"(d[0]), "+f"(d[1]), "+f"(d[2]), "+f"(d[3])
        : "r"(a0), "r"(a1), "r"(a2), "r"(a3), "r"(b0), "r"(b1));
}
// A-fragment word index for element (row r, col c) in a 16x8 tile (tiles of 128)
__device__ __forceinline__ int frIdx(int r, int c) {
    return (((r & 7) * 4 + (c & 3)) << 2) + ((r >> 3) & 1) + (((c >> 2) & 1) << 1);
}

// ---------------- init --------------------------------------------------------
__global__ void init_kernel(const float* __restrict__ X, float* __restrict__ out) {
    size_t g = (size_t)blockIdx.x * blockDim.x + threadIdx.x;
    out[g] = X[g & 127];
}

// ---------------- per-layer weight prep ---------------------------------------
__global__ void prep_kernel(const float* __restrict__ hW, const float* __restrict__ gW,
                            const float* __restrict__ gb, int l) {
    int g = blockIdx.x * blockDim.x + threadIdx.x;
    if (g < 8192) {
        int d = g >> 6, k = g & 63;
        g_hWt[g] = hW[(l * 64 + k) * 128 + d];
    }
    if (g < 24576) {
        int kc = g >> 7, d = g & 127;
        int c = kc >> 6, k = kc & 63;
        g_Gt[g] = gW[((l * 3 + c) * 128 + d) * 64 + k];
    }
    if (g < 128) {
        g_gbsum[g] = gb[(l * 3 + 0) * 128 + g] + gb[(l * 3 + 1) * 128 + g]
                   + gb[(l * 3 + 2) * 128 + g];
    }
}

// ---------------- generic tiled GEMM ------------------------------------------
__global__ __launch_bounds__(128) void gemm_kernel(
    const float* __restrict__ A, const float* __restrict__ B,
    const float* __restrict__ bias, float* __restrict__ C,
    int M, int K, int N, int accumulate)
{
    __shared__ __align__(16) float As[16][64];
    __shared__ __align__(16) float Bs[16][64];
    int t = threadIdx.x;
    int mT = blockIdx.x * 64, nT = blockIdx.y * 64;
    int tx = t & 7, ty = t >> 3;
    float acc[4][8];
#pragma unroll
    for (int r = 0; r < 4; r++)
#pragma unroll
        for (int c = 0; c < 8; c++) acc[r][c] = 0.f;

    for (int k0 = 0; k0 < K; k0 += 16) {
        {
            int row = t >> 1, kq = (t & 1) * 8;
            const float* ap = A + (size_t)(mT + row) * K + k0 + kq;
            float4 a0 = *(const float4*)ap;
            float4 a1 = *(const float4*)(ap + 4);
            As[kq + 0][row] = a0.x; As[kq + 1][row] = a0.y;
            As[kq + 2][row] = a0.z; As[kq + 3][row] = a0.w;
            As[kq + 4][row] = a1.x; As[kq + 5][row] = a1.y;
            As[kq + 6][row] = a1.z; As[kq + 7][row] = a1.w;
        }
        {
            int kr = t >> 3, nq = (t & 7) * 8;
            const float* bp = B + (size_t)(k0 + kr) * N + nT + nq;
            *(float4*)&Bs[kr][nq]     = *(const float4*)bp;
            *(float4*)&Bs[kr][nq + 4] = *(const float4*)(bp + 4);
        }
        __syncthreads();
#pragma unroll
        for (int kk = 0; kk < 16; kk++) {
            float4 a  = *(float4*)&As[kk][ty * 4];
            float4 b0 = *(float4*)&Bs[kk][tx * 8];
            float4 b1 = *(float4*)&Bs[kk][tx * 8 + 4];
            float av[4] = {a.x, a.y, a.z, a.w};
            float bv[8] = {b0.x, b0.y, b0.z, b0.w, b1.x, b1.y, b1.z, b1.w};
#pragma unroll
            for (int r = 0; r < 4; r++)
#pragma unroll
                for (int c = 0; c < 8; c++) acc[r][c] += av[r] * bv[c];
        }
        __syncthreads();
    }
#pragma unroll
    for (int r = 0; r < 4; r++) {
        int m = mT + ty * 4 + r;
        float* cp = C + (size_t)m * N + nT + tx * 8;
#pragma unroll
        for (int c = 0; c < 8; c++) {
            float v = acc[r][c] + bias[nT + tx * 8 + c];
            if (accumulate) v += cp[c];
            cp[c] = v;
        }
    }
}

// ---------------- tf32 MMA message kernel (msg = A@W2^T form) -------------------
// Grid 2048: block = (b, ihalf). 8 warps. Dynamic smem 67520 B.
// buf words: EsP[0..2048) dbl-buffered | Af[2048..3584) | W1p[3584..6656) |
// (nuc overlays: EsN[0..2048), AtN[2048..8192)) | W2f[8192..14336)
__global__ __launch_bounds__(256, 3) void msg_mma_kernel(
    const float* __restrict__ Ee, const float* __restrict__ Enuc,
    const float* __restrict__ wW1, const float* __restrict__ wb1,
    const float* __restrict__ wW2, const float* __restrict__ wb2,
    const float* __restrict__ Yp, int l)
{
    extern __shared__ __align__(16) unsigned dsm[];
    unsigned* buf  = dsm;                         // 14336 words
    float*    Hs   = (float*)(dsm + 14336);       // 2080 (stride 65), UNROUNDED
    float*    b1s  = (float*)(dsm + 16416);       // 144
    float*    b2e  = (float*)(dsm + 16560);       // 128 (ch 0,1)
    float*    Hsum = (float*)(dsm + 16688);       // 128
    float*    Ysum = (float*)(dsm + 16816);       // 64

    const int b = blockIdx.x >> 1, ihalf = blockIdx.x & 1;
    const int t = threadIdx.x, w = t >> 5, lane = t & 31;
    const int g = lane >> 2, tg = lane & 3;
    const int cls = w & 1, n0 = (w >> 1) * 2;
    const int i0 = ihalf * 16;

    // ---- fill smem ----
    for (int idx = t; idx < 2048; idx += 256) {
        int j = idx >> 6, k = idx & 63;
        Hs[j * 65 + k] = g_h[(size_t)b * 2048 + idx];
    }
    for (int idx = t; idx < 135; idx += 256)
        b1s[(idx / 45) * 48 + idx % 45] = wb1[l * 135 + idx];
    for (int idx = t; idx < 1536; idx += 256)   // Af zero (h>=45 stays 0)
        buf[2048 + idx] = 0u;
    for (int idx = t; idx < 3072; idx += 256) {   // W1 fragments, ch 0,1
        int tile = idx >> 6, l2 = idx & 63;
        int c = tile / 24, r = tile % 24;
        int nt = r >> 2, kt = r & 3;
        int ln = l2 >> 1, s = l2 & 1;
        int h = nt * 8 + (ln >> 2), f = kt * 8 + (ln & 3) + 4 * s;
        buf[3584 + idx] = (h < 45)
            ? f2tf(__ldg(&wW1[((size_t)(l * 3 + c) * 45 + h) * 32 + f])) : 0u;
    }
    for (int idx = t; idx < 6144; idx += 256) {   // W2 fragments, ch 0,1
        int tile = idx >> 6, l2 = idx & 63;
        int c = tile / 48, r = tile % 48;
        int ntile = r / 6, kt = r % 6;
        int ln = l2 >> 1, s = l2 & 1;
        int k = ntile * 8 + (ln >> 2);
        int h = kt * 8 + (ln & 3) + 4 * s;
        buf[8192 + idx] = (h < 45)
            ? f2tf(__ldg(&wW2[((size_t)(l * 3 + c) * 64 + k) * 45 + h])) : 0u;
    }
    if (t < 128) b2e[t] = wb2[l * 192 + t];
    __syncthreads();
    if (t < 128) {
        int c = t >> 6, k = t & 63;
        float s = 0.f;
        for (int j = 0; j < 16; j++) s += Hs[(c * 16 + j) * 65 + k];
        Hsum[t] = s;
    }
    if (t < 64) {
        float s = 0.f;
        for (int m = 0; m < 4; m++) s += __ldg(&Yp[m * 64 + t]);
        Ysum[t] = s;
    }
    // loop-invariant h values for the msg*h epilogue (8 regs)
    float hv[2][4];
#pragma unroll
    for (int ntl = 0; ntl < 2; ntl++) {
        int j0 = cls * 16 + g, j1 = j0 + 8;
        int k0 = (n0 + ntl) * 8 + 2 * tg;
        hv[ntl][0] = Hs[j0 * 65 + k0];
        hv[ntl][1] = Hs[j0 * 65 + k0 + 1];
        hv[ntl][2] = Hs[j1 * 65 + k0];
        hv[ntl][3] = Hs[j1 * 65 + k0 + 1];
    }
    const int c3 = ((cls == 0) == (ihalf == 0)) ? 0 : 1;

    // ---- initial E load (buffer 0) ----
    {
        int j = t >> 3, f4 = t & 7;
        float4 e4 = *(const float4*)(Ee + (((size_t)(b * 32 + i0)) * 32 + j) * 32 + 4 * f4);
        unsigned* p = &buf[((j >> 4) * 4 + (f4 >> 1)) * 128 + (j & 7) * 16
                           + ((j >> 3) & 1) + 2 * (f4 & 1)];
        p[0] = f2tf(e4.x); p[4] = f2tf(e4.y); p[8] = f2tf(e4.z); p[12] = f2tf(e4.w);
    }
    __syncthreads();

    // ================= electron edges =================
    for (int ii = 0; ii < 16; ii++) {
        const int i = i0 + ii;
        const int cur = (ii & 1) * 1024;
        if (ii < 15) {   // prefetch next E into other buffer
            int j = t >> 3, f4 = t & 7;
            float4 e4 = *(const float4*)(
                Ee + (((size_t)(b * 32 + i + 1)) * 32 + j) * 32 + 4 * f4);
            unsigned* p = &buf[(cur ^ 1024) + ((j >> 4) * 4 + (f4 >> 1)) * 128
                               + (j & 7) * 16 + ((j >> 3) & 1) + 2 * (f4 & 1)];
            p[0] = f2tf(e4.x); p[4] = f2tf(e4.y);
            p[8] = f2tf(e4.z); p[12] = f2tf(e4.w);
        }
        if (w < 6) {   // step1: A = ssp(E @ W1c^T + b1) -> Af (row=j, col=h)
#pragma unroll
            for (int mt = 0; mt < 2; mt++) {
                int c = ((mt == 0) == (ihalf == 0)) ? 0 : 1;
                float d[4] = {0.f, 0.f, 0.f, 0.f};
#pragma unroll
                for (int kt = 0; kt < 4; kt++) {
                    uint4 av = *(const uint4*)&buf[cur + (mt * 4 + kt) * 128 + lane * 4];
                    uint2 bv = *(const uint2*)&buf[3584 + (c * 24 + w * 4 + kt) * 64 + lane * 2];
                    mma8(d, av.x, av.y, av.z, av.w, bv.x, bv.y);
                }
                int h0 = w * 8 + 2 * tg, h1 = h0 + 1;
                int j0 = mt * 16 + g, j1 = j0 + 8;
                const float* bb = &b1s[c * 48];
                // Af tile = (j>>4)*6 + (h>>3); here j>>4 = mt, h>>3 = w
                unsigned* A = &buf[2048 + (mt * 6 + w) * 128];
                if (h0 < 45) {
                    A[frIdx(j0, h0)] = (j0 == i) ? 0u : f2tf(sspf(d[0] + bb[h0]));
                    A[frIdx(j1, h0)] = (j1 == i) ? 0u : f2tf(sspf(d[2] + bb[h0]));
                }
                if (h1 < 45) {
                    A[frIdx(j0, h1)] = (j0 == i) ? 0u : f2tf(sspf(d[1] + bb[h1]));
                    A[frIdx(j1, h1)] = (j1 == i) ? 0u : f2tf(sspf(d[3] + bb[h1]));
                }
            }
        }
        __syncthreads();
        {   // step2: msg = A_cls @ W2_c3^T  (K=48), then z[k] = sum_j msg*h
            float acc[2][4];
#pragma unroll
            for (int ntl = 0; ntl < 2; ntl++)
#pragma unroll
                for (int q = 0; q < 4; q++) acc[ntl][q] = 0.f;
#pragma unroll
            for (int kt = 0; kt < 6; kt++) {
                uint4 av = *(const uint4*)&buf[2048 + (cls * 6 + kt) * 128 + lane * 4];
#pragma unroll
                for (int ntl = 0; ntl < 2; ntl++) {
                    uint2 bv = *(const uint2*)&buf[8192
                                 + ((c3 * 8 + n0 + ntl) * 6 + kt) * 64 + lane * 2];
                    mma8(acc[ntl], av.x, av.y, av.z, av.w, bv.x, bv.y);
                }
            }
#pragma unroll
            for (int ntl = 0; ntl < 2; ntl++) {
                float s0 = acc[ntl][0] * hv[ntl][0] + acc[ntl][2] * hv[ntl][2];
                float s1 = acc[ntl][1] * hv[ntl][1] + acc[ntl][3] * hv[ntl][3];
#pragma unroll
                for (int m = 4; m <= 16; m <<= 1) {
                    s0 += __shfl_xor_sync(0xffffffffu, s0, m);
                    s1 += __shfl_xor_sync(0xffffffffu, s1, m);
                }
                if (g == 0) {
                    int k0 = (n0 + ntl) * 8 + 2 * tg;
                    float hs0 = Hsum[cls * 64 + k0]
                              - ((cls == ihalf) ? Hs[i * 65 + k0] : 0.f);
                    float hs1 = Hsum[cls * 64 + k0 + 1]
                              - ((cls == ihalf) ? Hs[i * 65 + k0 + 1] : 0.f);
                    float* zp = &g_z[((size_t)(b * 32 + i) * 3 + c3) * 64 + k0];
                    zp[0] = s0 + b2e[c3 * 64 + k0] * hs0;
                    zp[1] = s1 + b2e[c3 * 64 + k0 + 1] * hs1;
                }
            }
        }
        __syncthreads();
    }

    // ================= nuclear edges: 2 barriers total =================
    for (int idx = t; idx < 6144; idx += 256) buf[2048 + idx] = 0u;  // AtN zero
    {   // load E_nuc for all 16 i: row r = i_local*4 + m (64 rows x 32 f)
        int r = t >> 2, fb = (t & 3) * 8;
        const float* ep = Enuc + (((size_t)(b * 32 + i0 + (r >> 2))) * 4 + (r & 3)) * 32 + fb;
        float4 e0 = *(const float4*)ep;
        float4 e1 = *(const float4*)(ep + 4);
        unsigned* pb = &buf[((r >> 4) * 4 + (fb >> 3)) * 128];
        int lr = (r & 7) * 4, qr = (r >> 3) & 1;
        pb[(lr + 0) * 4 + qr]     = f2tf(e0.x);
        pb[(lr + 1) * 4 + qr]     = f2tf(e0.y);
        pb[(lr + 2) * 4 + qr]     = f2tf(e0.z);
        pb[(lr + 3) * 4 + qr]     = f2tf(e0.w);
        pb[(lr + 0) * 4 + qr + 2] = f2tf(e1.x);
        pb[(lr + 1) * 4 + qr + 2] = f2tf(e1.y);
        pb[(lr + 2) * 4 + qr + 2] = f2tf(e1.z);
        pb[(lr + 3) * 4 + qr + 2] = f2tf(e1.w);
    }
    __syncthreads();
    // phase A: step1 for all 16 i (24 tasks: mt 0..3 x nt 0..5)
#pragma unroll
    for (int s = 0; s < 3; s++) {
        int tau = w + 8 * s;
        int mt = tau / 6, nt = tau % 6;
        int hB = nt * 8 + g;
        float d[4] = {0.f, 0.f, 0.f, 0.f};
#pragma unroll
        for (int kt = 0; kt < 4; kt++) {
            uint4 av = *(const uint4*)&buf[(mt * 4 + kt) * 128 + lane * 4];
            unsigned bx = 0u, by = 0u;
            if (hB < 45) {
                const float* wp = &wW1[((size_t)(l * 3 + 2) * 45 + hB) * 32 + kt * 8 + tg];
                bx = f2tf(__ldg(wp)); by = f2tf(__ldg(wp + 4));
            }
            mma8(d, av.x, av.y, av.z, av.w, bx, by);
        }
        int h0 = nt * 8 + 2 * tg, h1 = h0 + 1;
        int r0 = mt * 16 + g, r1 = r0 + 8;
        if (h0 < 45) {
            buf[2048 + (r0 >> 2) * 384 + (h0 >> 4) * 128
                + (((h0 & 7) * 4 + (r0 & 3)) << 2) + ((h0 >> 3) & 1)]
                = f2tf(sspf(d[0] + b1s[96 + h0]));
            buf[2048 + (r1 >> 2) * 384 + (h0 >> 4) * 128
                + (((h0 & 7) * 4 + (r1 & 3)) << 2) + ((h0 >> 3) & 1)]
                = f2tf(sspf(d[2] + b1s[96 + h0]));
        }
        if (h1 < 45) {
            buf[2048 + (r0 >> 2) * 384 + (h1 >> 4) * 128
                + (((h1 & 7) * 4 + (r0 & 3)) << 2) + ((h1 >> 3) & 1)]
                = f2tf(sspf(d[1] + b1s[96 + h1]));
            buf[2048 + (r1 >> 2) * 384 + (h1 >> 4) * 128
                + (((h1 & 7) * 4 + (r1 & 3)) << 2) + ((h1 >> 3) & 1)]
                = f2tf(sspf(d[3] + b1s[96 + h1]));
        }
    }
    __syncthreads();
    // phase B: warp w owns k-tile w, sweeps all 16 i with no barriers
    {
        unsigned yb0 = f2tf(__ldg(&Yp[tg * 64 + w * 8 + g]));
        float w2n[2][3][2], b2n[2];
#pragma unroll
        for (int par = 0; par < 2; par++) {
            int k = w * 8 + 2 * tg + par;
            b2n[par] = __ldg(&wb2[(l * 3 + 2) * 64 + k]);
            const float* wp = wW2 + (size_t)((l * 3 + 2) * 64 + k) * 45;
#pragma unroll
            for (int mt = 0; mt < 3; mt++) {
                int h0 = mt * 16 + g, h1 = h0 + 8; if (h1 > 44) h1 = 44;
                w2n[par][mt][0] = __ldg(wp + h0);
                w2n[par][mt][1] = __ldg(wp + h1);
            }
        }
        for (int il = 0; il < 16; il++) {
            float facc[3][4];
#pragma unroll
            for (int mt = 0; mt < 3; mt++)
#pragma unroll
                for (int q = 0; q < 4; q++) facc[mt][q] = 0.f;
#pragma unroll
            for (int mt = 0; mt < 3; mt++) {
                uint4 av = *(const uint4*)&buf[2048 + il * 384 + mt * 128 + lane * 4];
                mma8(facc[mt], av.x, av.y, av.z, av.w, yb0, 0u);
            }
#pragma unroll
            for (int par = 0; par < 2; par++) {
                int k = w * 8 + 2 * tg + par;
                float s = 0.f;
#pragma unroll
                for (int mt = 0; mt < 3; mt++) {
                    s += facc[mt][par]     * w2n[par][mt][0];
                    s += facc[mt][par + 2] * w2n[par][mt][1];
                }
                s += __shfl_xor_sync(0xffffffffu, s, 4);
                s += __shfl_xor_sync(0xffffffffu, s, 8);
                s += __shfl_xor_sync(0xffffffffu, s, 16);
                if (g == 0) {
                    g_z[((size_t)(b * 32 + i0 + il) * 3 + 2) * 64 + k]
                        = s + b2n[par] * Ysum[k];
                }
            }
        }
    }
}

// ---------------- launch ------------------------------------------------------
extern "C" void kernel_launch(void* const* d_in, const int* in_sizes, int n_in,
                              void* d_out, int out_size) {
    const float* Ee  = (const float*)d_in[0];
    const float* En  = (const float*)d_in[1];
    const float* X   = (const float*)d_in[2];
    const float* Y   = (const float*)d_in[3];
    const float* wW1 = (const float*)d_in[4];
    const float* wb1 = (const float*)d_in[5];
    const float* wW2 = (const float*)d_in[6];
    const float* wb2 = (const float*)d_in[7];
    const float* hW  = (const float*)d_in[8];
    const float* hb  = (const float*)d_in[9];
    const float* gW  = (const float*)d_in[10];
    const float* gb  = (const float*)d_in[11];
    float* x = (float*)d_out;

    float *hbuf, *zbuf, *hWt, *Gt, *gbs;
    cudaGetSymbolAddress((void**)&hbuf, g_h);
    cudaGetSymbolAddress((void**)&zbuf, g_z);
    cudaGetSymbolAddress((void**)&hWt,  g_hWt);
    cudaGetSymbolAddress((void**)&Gt,   g_Gt);
    cudaGetSymbolAddress((void**)&gbs,  g_gbsum);

    const int MSG_SMEM = 16880 * 4;   // 67520 bytes
    cudaFuncSetAttribute(msg_mma_kernel,
                         cudaFuncAttributeMaxDynamicSharedMemorySize, MSG_SMEM);

    init_kernel<<<16384, 256>>>(X, x);
    for (int l = 0; l < 3; l++) {
        prep_kernel<<<96, 256>>>(hW, gW, gb, l);
        gemm_kernel<<<dim3(512, 1), 128>>>(x, hWt, hb + l * 64, hbuf,
                                           32768, 128, 64, 0);
        msg_mma_kernel<<<2048, 256, MSG_SMEM>>>(Ee, En, wW1, wb1, wW2, wb2, Y, l);
        gemm_kernel<<<dim3(512, 2), 128>>>(zbuf, Gt, gbs, x,
                                           32768, 192, 128, 1);
    }
}

// round 17
// speedup vs baseline: 1.6514x; 1.1609x over previous
#include <cuda_runtime.h>
#include <cstdint>

#define LOG2F_ 0.6931471805599453f

// ---------------- scratch (__device__ globals) --------------------------------
__device__ float g_h[32768 * 64];
__device__ float g_z[32768 * 192];
__device__ float g_Gn[128 * 192];     // gW[l] packed as [d][c*64+k]  (B operand)
__device__ float g_gbsum[128];

// ---------------- helpers -----------------------------------------------------
__device__ __forceinline__ unsigned f2tf(float f) {
    unsigned r;
    asm("cvt.rna.tf32.f32 %0, %1;" : "=r"(r) : "f"(f));
    return r;
}
__device__ __forceinline__ float sspf(float v) {
    return fmaxf(v, 0.f) + __logf(1.f + __expf(-fabsf(v))) - LOG2F_;
}
__device__ __forceinline__ void mma8(float d[4], unsigned a0, unsigned a1,
                                     unsigned a2, unsigned a3,
                                     unsigned b0, unsigned b1) {
    asm volatile(
        "mma.sync.aligned.m16n8k8.row.col.f32.tf32.tf32.f32 "
        "{%0,%1,%2,%3}, {%4,%5,%6,%7}, {%8,%9}, {%0,%1,%2,%3};"
        : "+f"(d[0]), "+f"(d[1]), "+f"(d[2]), "+f"(d[3])
        : "r"(a0), "r"(a1), "r"(a2), "r"(a3), "r"(b0), "r"(b1));
}
// A-fragment word index for element (row r, col c) in a 16x8 tile (tiles of 128)
__device__ __forceinline__ int frIdx(int r, int c) {
    return (((r & 7) * 4 + (c & 3)) << 2) + ((r >> 3) & 1) + (((c >> 2) & 1) << 1);
}

// ---------------- init --------------------------------------------------------
__global__ void init_kernel(const float* __restrict__ X, float* __restrict__ out) {
    size_t g = (size_t)blockIdx.x * blockDim.x + threadIdx.x;
    out[g] = X[g & 127];
}

// ---------------- per-layer weight prep ---------------------------------------
__global__ void prep_kernel(const float* __restrict__ gW,
                            const float* __restrict__ gb, int l) {
    int g = blockIdx.x * blockDim.x + threadIdx.x;
    if (g < 24576) {                 // Gn[d][c*64+k] = gW[l][c][d][k]
        int d = g / 192, r = g % 192;
        int c = r >> 6, k = r & 63;
        g_Gn[g] = gW[((l * 3 + c) * 128 + d) * 64 + k];
    }
    if (g < 128) {
        g_gbsum[g] = gb[(l * 3 + 0) * 128 + g] + gb[(l * 3 + 1) * 128 + g]
                   + gb[(l * 3 + 2) * 128 + g];
    }
}

// ---------------- tf32 tensor-core GEMM ----------------------------------------
// C[M,N] (+)= A[M,K] @ Bop^T + bias, where Bop is [N][K] row-major.
// Block tile 64x64, 256 threads = 8 warps (4m x 2n), BK=16.
__global__ __launch_bounds__(256) void gemm_tf32(
    const float* __restrict__ A, const float* __restrict__ Bop,
    const float* __restrict__ bias, float* __restrict__ C,
    int M, int K, int N, int accumulate)
{
    __shared__ __align__(16) unsigned As[64 * 20];
    __shared__ __align__(16) unsigned Bs[64 * 20];
    const int t = threadIdx.x, w = t >> 5, lane = t & 31;
    const int g = lane >> 2, tg = lane & 3;
    const int wm = w >> 1, wn = w & 1;
    const int mT = blockIdx.x * 64, nT = blockIdx.y * 64;
    const int m0 = wm * 16;

    float acc[4][4];
#pragma unroll
    for (int nt = 0; nt < 4; nt++)
#pragma unroll
        for (int q = 0; q < 4; q++) acc[nt][q] = 0.f;

    const int lrow = t >> 2, lkq = (t & 3) * 4;
    for (int k0 = 0; k0 < K; k0 += 16) {
        {
            float4 a4 = *(const float4*)(A + (size_t)(mT + lrow) * K + k0 + lkq);
            unsigned* p = &As[lrow * 20 + lkq];
            p[0] = f2tf(a4.x); p[1] = f2tf(a4.y); p[2] = f2tf(a4.z); p[3] = f2tf(a4.w);
            float4 b4 = *(const float4*)(Bop + (size_t)(nT + lrow) * K + k0 + lkq);
            unsigned* q = &Bs[lrow * 20 + lkq];
            q[0] = f2tf(b4.x); q[1] = f2tf(b4.y); q[2] = f2tf(b4.z); q[3] = f2tf(b4.w);
        }
        __syncthreads();
#pragma unroll
        for (int k8 = 0; k8 < 16; k8 += 8) {
            unsigned a0 = As[(m0 + g) * 20 + k8 + tg];
            unsigned a1 = As[(m0 + g + 8) * 20 + k8 + tg];
            unsigned a2 = As[(m0 + g) * 20 + k8 + tg + 4];
            unsigned a3 = As[(m0 + g + 8) * 20 + k8 + tg + 4];
#pragma unroll
            for (int nt = 0; nt < 4; nt++) {
                unsigned b0 = Bs[(wn * 32 + nt * 8 + g) * 20 + k8 + tg];
                unsigned b1 = Bs[(wn * 32 + nt * 8 + g) * 20 + k8 + tg + 4];
                mma8(acc[nt], a0, a1, a2, a3, b0, b1);
            }
        }
        __syncthreads();
    }
    // epilogue
#pragma unroll
    for (int nt = 0; nt < 4; nt++) {
        int n0 = nT + wn * 32 + nt * 8 + 2 * tg;
        float bb0 = bias[n0], bb1 = bias[n0 + 1];
        int row0 = mT + m0 + g, row1 = row0 + 8;
        float* c0 = C + (size_t)row0 * N + n0;
        float* c1 = C + (size_t)row1 * N + n0;
        if (accumulate) {
            c0[0] += acc[nt][0] + bb0; c0[1] += acc[nt][1] + bb1;
            c1[0] += acc[nt][2] + bb0; c1[1] += acc[nt][3] + bb1;
        } else {
            c0[0] = acc[nt][0] + bb0;  c0[1] = acc[nt][1] + bb1;
            c1[0] = acc[nt][2] + bb0;  c1[1] = acc[nt][3] + bb1;
        }
    }
}

// ---------------- tf32 MMA message kernel (msg = A@W2^T form) -------------------
// Grid 2048: block = (b, ihalf). 8 warps. Dynamic smem 67520 B.
// buf words: EsP[0..2048) dbl-buffered | Af[2048..3584) | W1p[3584..6656) |
// (nuc overlays: EsN[0..2048), AtN[2048..8192)) | W2f[8192..14336)
__global__ __launch_bounds__(256, 3) void msg_mma_kernel(
    const float* __restrict__ Ee, const float* __restrict__ Enuc,
    const float* __restrict__ wW1, const float* __restrict__ wb1,
    const float* __restrict__ wW2, const float* __restrict__ wb2,
    const float* __restrict__ Yp, int l)
{
    extern __shared__ __align__(16) unsigned dsm[];
    unsigned* buf  = dsm;                         // 14336 words
    float*    Hs   = (float*)(dsm + 14336);       // 2080 (stride 65), UNROUNDED
    float*    b1s  = (float*)(dsm + 16416);       // 144
    float*    b2e  = (float*)(dsm + 16560);       // 128 (ch 0,1)
    float*    Hsum = (float*)(dsm + 16688);       // 128
    float*    Ysum = (float*)(dsm + 16816);       // 64

    const int b = blockIdx.x >> 1, ihalf = blockIdx.x & 1;
    const int t = threadIdx.x, w = t >> 5, lane = t & 31;
    const int g = lane >> 2, tg = lane & 3;
    const int cls = w & 1, n0 = (w >> 1) * 2;
    const int i0 = ihalf * 16;

    // ---- fill smem ----
    for (int idx = t; idx < 2048; idx += 256) {
        int j = idx >> 6, k = idx & 63;
        Hs[j * 65 + k] = g_h[(size_t)b * 2048 + idx];
    }
    for (int idx = t; idx < 135; idx += 256)
        b1s[(idx / 45) * 48 + idx % 45] = wb1[l * 135 + idx];
    for (int idx = t; idx < 1536; idx += 256)   // Af zero (h>=45 stays 0)
        buf[2048 + idx] = 0u;
    for (int idx = t; idx < 3072; idx += 256) {   // W1 fragments, ch 0,1
        int tile = idx >> 6, l2 = idx & 63;
        int c = tile / 24, r = tile % 24;
        int nt = r >> 2, kt = r & 3;
        int ln = l2 >> 1, s = l2 & 1;
        int h = nt * 8 + (ln >> 2), f = kt * 8 + (ln & 3) + 4 * s;
        buf[3584 + idx] = (h < 45)
            ? f2tf(__ldg(&wW1[((size_t)(l * 3 + c) * 45 + h) * 32 + f])) : 0u;
    }
    for (int idx = t; idx < 6144; idx += 256) {   // W2 fragments, ch 0,1
        int tile = idx >> 6, l2 = idx & 63;
        int c = tile / 48, r = tile % 48;
        int ntile = r / 6, kt = r % 6;
        int ln = l2 >> 1, s = l2 & 1;
        int k = ntile * 8 + (ln >> 2);
        int h = kt * 8 + (ln & 3) + 4 * s;
        buf[8192 + idx] = (h < 45)
            ? f2tf(__ldg(&wW2[((size_t)(l * 3 + c) * 64 + k) * 45 + h])) : 0u;
    }
    if (t < 128) b2e[t] = wb2[l * 192 + t];
    __syncthreads();
    if (t < 128) {
        int c = t >> 6, k = t & 63;
        float s = 0.f;
        for (int j = 0; j < 16; j++) s += Hs[(c * 16 + j) * 65 + k];
        Hsum[t] = s;
    }
    if (t < 64) {
        float s = 0.f;
        for (int m = 0; m < 4; m++) s += __ldg(&Yp[m * 64 + t]);
        Ysum[t] = s;
    }
    // loop-invariant h values for the msg*h epilogue (8 regs)
    float hv[2][4];
#pragma unroll
    for (int ntl = 0; ntl < 2; ntl++) {
        int j0 = cls * 16 + g, j1 = j0 + 8;
        int k0 = (n0 + ntl) * 8 + 2 * tg;
        hv[ntl][0] = Hs[j0 * 65 + k0];
        hv[ntl][1] = Hs[j0 * 65 + k0 + 1];
        hv[ntl][2] = Hs[j1 * 65 + k0];
        hv[ntl][3] = Hs[j1 * 65 + k0 + 1];
    }
    const int c3 = ((cls == 0) == (ihalf == 0)) ? 0 : 1;

    // ---- initial E load (buffer 0) ----
    {
        int j = t >> 3, f4 = t & 7;
        float4 e4 = *(const float4*)(Ee + (((size_t)(b * 32 + i0)) * 32 + j) * 32 + 4 * f4);
        unsigned* p = &buf[((j >> 4) * 4 + (f4 >> 1)) * 128 + (j & 7) * 16
                           + ((j >> 3) & 1) + 2 * (f4 & 1)];
        p[0] = f2tf(e4.x); p[4] = f2tf(e4.y); p[8] = f2tf(e4.z); p[12] = f2tf(e4.w);
    }
    __syncthreads();

    // ================= electron edges =================
    for (int ii = 0; ii < 16; ii++) {
        const int i = i0 + ii;
        const int cur = (ii & 1) * 1024;
        if (ii < 15) {   // prefetch next E into other buffer
            int j = t >> 3, f4 = t & 7;
            float4 e4 = *(const float4*)(
                Ee + (((size_t)(b * 32 + i + 1)) * 32 + j) * 32 + 4 * f4);
            unsigned* p = &buf[(cur ^ 1024) + ((j >> 4) * 4 + (f4 >> 1)) * 128
                               + (j & 7) * 16 + ((j >> 3) & 1) + 2 * (f4 & 1)];
            p[0] = f2tf(e4.x); p[4] = f2tf(e4.y);
            p[8] = f2tf(e4.z); p[12] = f2tf(e4.w);
        }
        if (w < 6) {   // step1: A = ssp(E @ W1c^T + b1) -> Af (row=j, col=h)
#pragma unroll
            for (int mt = 0; mt < 2; mt++) {
                int c = ((mt == 0) == (ihalf == 0)) ? 0 : 1;
                float d[4] = {0.f, 0.f, 0.f, 0.f};
#pragma unroll
                for (int kt = 0; kt < 4; kt++) {
                    uint4 av = *(const uint4*)&buf[cur + (mt * 4 + kt) * 128 + lane * 4];
                    uint2 bv = *(const uint2*)&buf[3584 + (c * 24 + w * 4 + kt) * 64 + lane * 2];
                    mma8(d, av.x, av.y, av.z, av.w, bv.x, bv.y);
                }
                int h0 = w * 8 + 2 * tg, h1 = h0 + 1;
                int j0 = mt * 16 + g, j1 = j0 + 8;
                const float* bb = &b1s[c * 48];
                // Af tile = (j>>4)*6 + (h>>3); here j>>4 = mt, h>>3 = w
                unsigned* A = &buf[2048 + (mt * 6 + w) * 128];
                if (h0 < 45) {
                    A[frIdx(j0, h0)] = (j0 == i) ? 0u : f2tf(sspf(d[0] + bb[h0]));
                    A[frIdx(j1, h0)] = (j1 == i) ? 0u : f2tf(sspf(d[2] + bb[h0]));
                }
                if (h1 < 45) {
                    A[frIdx(j0, h1)] = (j0 == i) ? 0u : f2tf(sspf(d[1] + bb[h1]));
                    A[frIdx(j1, h1)] = (j1 == i) ? 0u : f2tf(sspf(d[3] + bb[h1]));
                }
            }
        }
        __syncthreads();
        {   // step2: msg = A_cls @ W2_c3^T  (K=48), then z[k] = sum_j msg*h
            float acc[2][4];
#pragma unroll
            for (int ntl = 0; ntl < 2; ntl++)
#pragma unroll
                for (int q = 0; q < 4; q++) acc[ntl][q] = 0.f;
#pragma unroll
            for (int kt = 0; kt < 6; kt++) {
                uint4 av = *(const uint4*)&buf[2048 + (cls * 6 + kt) * 128 + lane * 4];
#pragma unroll
                for (int ntl = 0; ntl < 2; ntl++) {
                    uint2 bv = *(const uint2*)&buf[8192
                                 + ((c3 * 8 + n0 + ntl) * 6 + kt) * 64 + lane * 2];
                    mma8(acc[ntl], av.x, av.y, av.z, av.w, bv.x, bv.y);
                }
            }
#pragma unroll
            for (int ntl = 0; ntl < 2; ntl++) {
                float s0 = acc[ntl][0] * hv[ntl][0] + acc[ntl][2] * hv[ntl][2];
                float s1 = acc[ntl][1] * hv[ntl][1] + acc[ntl][3] * hv[ntl][3];
#pragma unroll
                for (int m = 4; m <= 16; m <<= 1) {
                    s0 += __shfl_xor_sync(0xffffffffu, s0, m);
                    s1 += __shfl_xor_sync(0xffffffffu, s1, m);
                }
                if (g == 0) {
                    int k0 = (n0 + ntl) * 8 + 2 * tg;
                    float hs0 = Hsum[cls * 64 + k0]
                              - ((cls == ihalf) ? Hs[i * 65 + k0] : 0.f);
                    float hs1 = Hsum[cls * 64 + k0 + 1]
                              - ((cls == ihalf) ? Hs[i * 65 + k0 + 1] : 0.f);
                    float* zp = &g_z[((size_t)(b * 32 + i) * 3 + c3) * 64 + k0];
                    zp[0] = s0 + b2e[c3 * 64 + k0] * hs0;
                    zp[1] = s1 + b2e[c3 * 64 + k0 + 1] * hs1;
                }
            }
        }
        __syncthreads();
    }

    // ================= nuclear edges: 2 barriers total =================
    for (int idx = t; idx < 6144; idx += 256) buf[2048 + idx] = 0u;  // AtN zero
    {   // load E_nuc for all 16 i: row r = i_local*4 + m (64 rows x 32 f)
        int r = t >> 2, fb = (t & 3) * 8;
        const float* ep = Enuc + (((size_t)(b * 32 + i0 + (r >> 2))) * 4 + (r & 3)) * 32 + fb;
        float4 e0 = *(const float4*)ep;
        float4 e1 = *(const float4*)(ep + 4);
        unsigned* pb = &buf[((r >> 4) * 4 + (fb >> 3)) * 128];
        int lr = (r & 7) * 4, qr = (r >> 3) & 1;
        pb[(lr + 0) * 4 + qr]     = f2tf(e0.x);
        pb[(lr + 1) * 4 + qr]     = f2tf(e0.y);
        pb[(lr + 2) * 4 + qr]     = f2tf(e0.z);
        pb[(lr + 3) * 4 + qr]     = f2tf(e0.w);
        pb[(lr + 0) * 4 + qr + 2] = f2tf(e1.x);
        pb[(lr + 1) * 4 + qr + 2] = f2tf(e1.y);
        pb[(lr + 2) * 4 + qr + 2] = f2tf(e1.z);
        pb[(lr + 3) * 4 + qr + 2] = f2tf(e1.w);
    }
    __syncthreads();
    // phase A: step1 for all 16 i (24 tasks: mt 0..3 x nt 0..5)
#pragma unroll
    for (int s = 0; s < 3; s++) {
        int tau = w + 8 * s;
        int mt = tau / 6, nt = tau % 6;
        int hB = nt * 8 + g;
        float d[4] = {0.f, 0.f, 0.f, 0.f};
#pragma unroll
        for (int kt = 0; kt < 4; kt++) {
            uint4 av = *(const uint4*)&buf[(mt * 4 + kt) * 128 + lane * 4];
            unsigned bx = 0u, by = 0u;
            if (hB < 45) {
                const float* wp = &wW1[((size_t)(l * 3 + 2) * 45 + hB) * 32 + kt * 8 + tg];
                bx = f2tf(__ldg(wp)); by = f2tf(__ldg(wp + 4));
            }
            mma8(d, av.x, av.y, av.z, av.w, bx, by);
        }
        int h0 = nt * 8 + 2 * tg, h1 = h0 + 1;
        int r0 = mt * 16 + g, r1 = r0 + 8;
        if (h0 < 45) {
            buf[2048 + (r0 >> 2) * 384 + (h0 >> 4) * 128
                + (((h0 & 7) * 4 + (r0 & 3)) << 2) + ((h0 >> 3) & 1)]
                = f2tf(sspf(d[0] + b1s[96 + h0]));
            buf[2048 + (r1 >> 2) * 384 + (h0 >> 4) * 128
                + (((h0 & 7) * 4 + (r1 & 3)) << 2) + ((h0 >> 3) & 1)]
                = f2tf(sspf(d[2] + b1s[96 + h0]));
        }
        if (h1 < 45) {
            buf[2048 + (r0 >> 2) * 384 + (h1 >> 4) * 128
                + (((h1 & 7) * 4 + (r0 & 3)) << 2) + ((h1 >> 3) & 1)]
                = f2tf(sspf(d[1] + b1s[96 + h1]));
            buf[2048 + (r1 >> 2) * 384 + (h1 >> 4) * 128
                + (((h1 & 7) * 4 + (r1 & 3)) << 2) + ((h1 >> 3) & 1)]
                = f2tf(sspf(d[3] + b1s[96 + h1]));
        }
    }
    __syncthreads();
    // phase B: warp w owns k-tile w, sweeps all 16 i with no barriers
    {
        unsigned yb0 = f2tf(__ldg(&Yp[tg * 64 + w * 8 + g]));
        float w2n[2][3][2], b2n[2];
#pragma unroll
        for (int par = 0; par < 2; par++) {
            int k = w * 8 + 2 * tg + par;
            b2n[par] = __ldg(&wb2[(l * 3 + 2) * 64 + k]);
            const float* wp = wW2 + (size_t)((l * 3 + 2) * 64 + k) * 45;
#pragma unroll
            for (int mt = 0; mt < 3; mt++) {
                int h0 = mt * 16 + g, h1 = h0 + 8; if (h1 > 44) h1 = 44;
                w2n[par][mt][0] = __ldg(wp + h0);
                w2n[par][mt][1] = __ldg(wp + h1);
            }
        }
        for (int il = 0; il < 16; il++) {
            float facc[3][4];
#pragma unroll
            for (int mt = 0; mt < 3; mt++)
#pragma unroll
                for (int q = 0; q < 4; q++) facc[mt][q] = 0.f;
#pragma unroll
            for (int mt = 0; mt < 3; mt++) {
                uint4 av = *(const uint4*)&buf[2048 + il * 384 + mt * 128 + lane * 4];
                mma8(facc[mt], av.x, av.y, av.z, av.w, yb0, 0u);
            }
#pragma unroll
            for (int par = 0; par < 2; par++) {
                int k = w * 8 + 2 * tg + par;
                float s = 0.f;
#pragma unroll
                for (int mt = 0; mt < 3; mt++) {
                    s += facc[mt][par]     * w2n[par][mt][0];
                    s += facc[mt][par + 2] * w2n[par][mt][1];
                }
                s += __shfl_xor_sync(0xffffffffu, s, 4);
                s += __shfl_xor_sync(0xffffffffu, s, 8);
                s += __shfl_xor_sync(0xffffffffu, s, 16);
                if (g == 0) {
                    g_z[((size_t)(b * 32 + i0 + il) * 3 + 2) * 64 + k]
                        = s + b2n[par] * Ysum[k];
                }
            }
        }
    }
}

// ---------------- launch ------------------------------------------------------
extern "C" void kernel_launch(void* const* d_in, const int* in_sizes, int n_in,
                              void* d_out, int out_size) {
    const float* Ee  = (const float*)d_in[0];
    const float* En  = (const float*)d_in[1];
    const float* X   = (const float*)d_in[2];
    const float* Y   = (const float*)d_in[3];
    const float* wW1 = (const float*)d_in[4];
    const float* wb1 = (const float*)d_in[5];
    const float* wW2 = (const float*)d_in[6];
    const float* wb2 = (const float*)d_in[7];
    const float* hW  = (const float*)d_in[8];
    const float* hb  = (const float*)d_in[9];
    const float* gW  = (const float*)d_in[10];
    const float* gb  = (const float*)d_in[11];
    float* x = (float*)d_out;

    float *hbuf, *zbuf, *Gn, *gbs;
    cudaGetSymbolAddress((void**)&hbuf, g_h);
    cudaGetSymbolAddress((void**)&zbuf, g_z);
    cudaGetSymbolAddress((void**)&Gn,   g_Gn);
    cudaGetSymbolAddress((void**)&gbs,  g_gbsum);

    const int MSG_SMEM = 16880 * 4;   // 67520 bytes
    cudaFuncSetAttribute(msg_mma_kernel,
                         cudaFuncAttributeMaxDynamicSharedMemorySize, MSG_SMEM);

    init_kernel<<<16384, 256>>>(X, x);
    for (int l = 0; l < 3; l++) {
        prep_kernel<<<96, 256>>>(gW, gb, l);
        // h = x @ hW[l]^T + hb[l]; B operand = hW[l] ([64][128] = [N][K])
        gemm_tf32<<<dim3(512, 1), 256>>>(x, hW + (size_t)l * 64 * 128,
                                         hb + l * 64, hbuf, 32768, 128, 64, 0);
        msg_mma_kernel<<<2048, 256, MSG_SMEM>>>(Ee, En, wW1, wb1, wW2, wb2, Y, l);
        // x += z @ Gn^T + gbsum; B operand = Gn ([128][192] = [N][K])
        gemm_tf32<<<dim3(512, 2), 256>>>(zbuf, Gn, gbs, x, 32768, 192, 128, 1);
    }
}